// round 10
// baseline (speedup 1.0000x reference)
#include <cuda_runtime.h>

#define N     8192
#define D     256
#define D4    64            // D/4
#define NCLS  10
#define NBK   128           // accumulate blocks (one wave, <=148 SMs)
#define RPB   64            // rows per block
#define RPT   8             // rows per subgroup per tile
#define TILES 2
#define SDIM  (NCLS * D)    // 2560
#define SDIM4 (NCLS * D4)   // 640
#define REC   2580          // record: 2560 S + 10 Q + 10 counts (as float)
#define NGRP  16            // reduction groups
#define GSZ   8             // blocks per group

// Scratch: records fully overwritten every replay; counters reset by the
// final elected block -> graph-replay safe, no allocations, no zero kernel.
__device__ float g_part[NBK][REC];    // 1.32 MB
__device__ float g_mid[NGRP][REC];    // 165 KB
__device__ int   g_gctr[NGRP];
__device__ int   g_fctr;

__device__ __forceinline__ double block_reduce(double v, double* red, int t) {
    __syncthreads();
    red[t] = v;
    __syncthreads();
    #pragma unroll
    for (int s2 = 128; s2; s2 >>= 1) {
        if (t < s2) red[t] += red[t + s2];
        __syncthreads();
    }
    return red[0];
}

// ---------------------------------------------------------------------------
// Single kernel. Phase A: stream input (proven R7 loop). Phase B: last block
// of each 8-group reduces the group. Phase C: last mid-reducer does the
// final 16-way reduce into shared and the epilogue. No spins, no hot atomics.
// ---------------------------------------------------------------------------
__global__ void __launch_bounds__(256) k_all(const float* __restrict__ x,
                                             const int* __restrict__ lab,
                                             float* __restrict__ res) {
    __shared__ float4 Ssh[4][SDIM4];     // 40 KB; reused as final record buf
    __shared__ double red[256];
    __shared__ float  qred[8][NCLS];
    __shared__ int    labs[RPB];
    __shared__ int    flag;

    const int tid = threadIdx.x;
    const int sg  = tid >> 6;            // subgroup 0..3
    const int t   = tid & 63;            // dim-group 0..63
    const int b   = blockIdx.x;
    const int grp = b >> 3;              // group 0..15

    // ---------------- Phase A: accumulate 64 rows --------------------------
    if (tid < RPB) labs[tid] = lab[b * RPB + tid];
    __syncthreads();

    float4 S[NCLS];
    float  Q[NCLS];
    #pragma unroll
    for (int k = 0; k < NCLS; k++) {
        S[k] = make_float4(0.f, 0.f, 0.f, 0.f);
        Q[k] = 0.f;
    }

    const float4* __restrict__ p =
        reinterpret_cast<const float4*>(x) + (size_t)(b * RPB + sg * RPT) * D4 + t;

#define BODY(k) { S[k].x += v[r].x; S[k].y += v[r].y;                          \
                  S[k].z += v[r].z; S[k].w += v[r].w; Q[k] += q; }
    #pragma unroll
    for (int tile = 0; tile < TILES; tile++) {
        float4 v[RPT];
        #pragma unroll
        for (int r = 0; r < RPT; r++) v[r] = p[(tile * 32 + r) * D4];
        #pragma unroll
        for (int r = 0; r < RPT; r++) {
            const int l = labs[tile * 32 + sg * RPT + r];
            float q = v[r].x * v[r].x;
            q = fmaf(v[r].y, v[r].y, q);
            q = fmaf(v[r].z, v[r].z, q);
            q = fmaf(v[r].w, v[r].w, q);
            if      (l == 0) BODY(0)
            else if (l == 1) BODY(1)
            else if (l == 2) BODY(2)
            else if (l == 3) BODY(3)
            else if (l == 4) BODY(4)
            else if (l == 5) BODY(5)
            else if (l == 6) BODY(6)
            else if (l == 7) BODY(7)
            else if (l == 8) BODY(8)
            else             BODY(9)
        }
    }
#undef BODY

    #pragma unroll
    for (int k = 0; k < NCLS; k++) Ssh[sg][k * D4 + t] = S[k];
    __syncthreads();

    // Merge 4 subgroup buffers -> g_part[b][0..2559].
    float4* dst = reinterpret_cast<float4*>(g_part[b]);
    #pragma unroll
    for (int i = tid; i < SDIM4; i += 256) {
        float4 a = Ssh[0][i], b1 = Ssh[1][i], c = Ssh[2][i], d = Ssh[3][i];
        a.x += b1.x; a.y += b1.y; a.z += b1.z; a.w += b1.w;
        c.x += d.x;  c.y += d.y;  c.z += d.z;  c.w += d.w;
        a.x += c.x;  a.y += c.y;  a.z += c.z;  a.w += c.w;
        dst[i] = a;
    }

    // Q -> g_part[b][2560+k].
    const int lane = tid & 31, w = tid >> 5;
    #pragma unroll
    for (int k = 0; k < NCLS; k++) {
        float vq = Q[k];
        #pragma unroll
        for (int off = 16; off; off >>= 1)
            vq += __shfl_down_sync(0xffffffffu, vq, off);
        if (lane == 0) qred[w][k] = vq;
    }
    __syncthreads();
    if (tid < NCLS) {
        float s = 0.f;
        #pragma unroll
        for (int w2 = 0; w2 < 8; w2++) s += qred[w2][tid];
        g_part[b][SDIM + tid] = s;
        // Counts: thread k scans the 64 cached labels (shared, cheap).
        int c = 0;
        #pragma unroll
        for (int i = 0; i < RPB; i++) c += (labs[i] == tid) ? 1 : 0;
        g_part[b][SDIM + NCLS + tid] = (float)c;
    }

    // ---------------- Phase B election: last of 8 in group reduces ---------
    __threadfence();
    __syncthreads();
    if (tid == 0)
        flag = (atomicAdd(&g_gctr[grp], 1) == GSZ - 1) ? 1 : 0;
    __syncthreads();
    if (!flag) return;
    __threadfence();   // acquire peers' records

    {
        const int b0 = grp * GSZ;
        for (int i = tid; i < REC; i += 256) {
            float v[GSZ];
            #pragma unroll
            for (int j = 0; j < GSZ; j++) v[j] = g_part[b0 + j][i];
            g_mid[grp][i] = ((v[0] + v[1]) + (v[2] + v[3])) +
                            ((v[4] + v[5]) + (v[6] + v[7]));
        }
    }

    // ---------------- Phase C election: last of 16 finishes ---------------
    __threadfence();
    __syncthreads();
    if (tid == 0)
        flag = (atomicAdd(&g_fctr, 1) == NGRP - 1) ? 1 : 0;
    __syncthreads();
    if (!flag) return;
    __threadfence();   // acquire mid records

    // Final 16-way reduce into shared (reuse Ssh as flat float buffer).
    float* shf = reinterpret_cast<float*>(Ssh);
    for (int i = tid; i < REC; i += 256) {
        float v[NGRP];
        #pragma unroll
        for (int j = 0; j < NGRP; j++) v[j] = g_mid[j][i];
        float s = 0.f;
        #pragma unroll
        for (int j = 0; j < NGRP; j++) s += v[j];
        shf[i] = s;
    }
    __syncthreads();

    // ---------------- Epilogue (thread t2 = dim t2) ------------------------
    const int t2 = tid;
    const int firstL = lab[0];
    const int lastL  = lab[N - 1];
    const float v0 = x[t2];
    const float vN = x[(size_t)(N - 1) * D + t2];

    double dsame = 0.0;
    float satot = 0.f, sbtot = 0.f;
    #pragma unroll
    for (int l = 0; l < NCLS; l++) {
        float sv = shf[l * D + t2];
        float sa = sv - ((l == lastL)  ? vN : 0.f);   // rows i in [0, N-1)
        float sb = sv - ((l == firstL) ? v0 : 0.f);   // cols j in [1, N)
        dsame += (double)sa * (double)sb;
        satot += sa; sbtot += sb;
    }
    const double dall = (double)satot * (double)sbtot;

    const double dsame_t = block_reduce(dsame, red, t2);
    const double dall_t  = block_reduce(dall,  red, t2);
    const double sq0_t   = block_reduce((double)v0 * v0, red, t2);
    const double sqN_t   = block_reduce((double)vN * vN, red, t2);

    if (t2 == 0) {
        double term12 = 0.0;
        #pragma unroll
        for (int l = 0; l < NCLS; l++) {
            double sqA = (double)shf[SDIM + l] - ((l == lastL)  ? sqN_t : 0.0);
            double sqB = (double)shf[SDIM + l] - ((l == firstL) ? sq0_t : 0.0);
            double cnt = (double)shf[SDIM + NCLS + l];
            double cA  = cnt - ((l == lastL)  ? 1.0 : 0.0);
            double cB  = cnt - ((l == firstL) ? 1.0 : 0.0);
            term12 += sqA * (2.0 * cB - (double)(N - 1))
                    + sqB * (2.0 * cA - (double)(N - 1));
        }
        double result = term12 - 2.0 * (2.0 * dsame_t - dall_t);
        const double PAR = 0.5 / (double)N;   // COV * 0.5 / BATCH_SIZE
        res[0] = (float)(PAR * result);
    }

    // Reset counters for the next graph replay.
    __syncthreads();
    if (tid < NGRP) g_gctr[tid] = 0;
    if (tid == 0)   g_fctr = 0;
}

extern "C" void kernel_launch(void* const* d_in, const int* in_sizes, int n_in,
                              void* d_out, int out_size) {
    const float* x   = (const float*)d_in[0];
    const int*   lab = (const int*)d_in[1];
    float*       res = (float*)d_out;
    (void)in_sizes; (void)n_in; (void)out_size;

    k_all<<<NBK, 256>>>(x, lab, res);
}

// round 12
// speedup vs baseline: 1.2961x; 1.2961x over previous
#include <cuda_runtime.h>

#define N     8192
#define D     256
#define NCLS  10
#define NCH   8             // dim chunks (32 floats each)
#define CHW   32            // chunk width (floats)
#define NRG   16            // row groups
#define RPG   512           // rows per group
#define NBK   (NCH * NRG)   // 128 blocks
#define RPW   64            // rows per warp
#define RECF  340           // record: 320 S + 10 Q + 10 counts

// Scratch: records fully overwritten every replay; counters reset by final
// block -> graph-replay safe, no allocation, no zeroing kernel.
__device__ float  g_rec[NBK][RECF];   // 174 KB
__device__ double g_contrib[NCH];
__device__ int    g_gctr[NCH];
__device__ int    g_fctr;

// ---------------------------------------------------------------------------
// Single kernel, dimension-partitioned.
// Phase A (128 blocks): block (g,c) accumulates per-class sums for its 32
//   dims over its 512 rows. Lane = dim -> labels warp-uniform -> branch tree.
// Phase B (8 chunk leaders): sum 16 row-group records -> complete per-class
//   sums for the chunk -> fold to ONE scalar contribution (all terms are
//   dim-separable).
// Phase C (last leader): sum 8 doubles, scale, store. Reset counters.
// ---------------------------------------------------------------------------
__global__ void __launch_bounds__(256) k_all(const float* __restrict__ x,
                                             const int* __restrict__ lab,
                                             float* __restrict__ res) {
    __shared__ int    labs[RPG];           // 2 KB
    __shared__ float  shS[8][NCLS * CHW];  // 10 KB
    __shared__ float  shQ[8][NCLS];
    __shared__ int    shC[8][NCLS];
    __shared__ float  tot[RECF];
    __shared__ float  x0c[CHW], xNc[CHW];
    __shared__ int    l0N[2];
    __shared__ int    flag;

    const int tid  = threadIdx.x;
    const int w    = tid >> 5;
    const int lane = tid & 31;
    const int b    = blockIdx.x;
    const int c    = b & (NCH - 1);        // dim chunk 0..7
    const int g    = b >> 3;               // row group 0..15

    // ---------------- Phase A ---------------------------------------------
    for (int i = tid; i < RPG; i += 256) labs[i] = lab[g * RPG + i];
    __syncthreads();

    float S[NCLS], Q[NCLS];
    int   C[NCLS];
    #pragma unroll
    for (int k = 0; k < NCLS; k++) { S[k] = 0.f; Q[k] = 0.f; C[k] = 0; }

    // Warp w handles rows [g*512 + w*64, +64); lane owns dim c*32+lane.
    const float* __restrict__ base =
        x + (size_t)(g * RPG + w * RPW) * D + c * CHW + lane;

#define BODY(k) { S[k] += v[j]; Q[k] += q; C[k]++; }
    for (int r0 = 0; r0 < RPW; r0 += 8) {
        float v[8];
        int   ll[8];
        #pragma unroll
        for (int j = 0; j < 8; j++) v[j] = base[(r0 + j) * D];
        #pragma unroll
        for (int j = 0; j < 8; j++) ll[j] = labs[w * RPW + r0 + j];
        #pragma unroll
        for (int j = 0; j < 8; j++) {
            const int l = ll[j];           // uniform across warp
            const float q = v[j] * v[j];
            if      (l == 0) BODY(0)
            else if (l == 1) BODY(1)
            else if (l == 2) BODY(2)
            else if (l == 3) BODY(3)
            else if (l == 4) BODY(4)
            else if (l == 5) BODY(5)
            else if (l == 6) BODY(6)
            else if (l == 7) BODY(7)
            else if (l == 8) BODY(8)
            else             BODY(9)
        }
    }
#undef BODY

    // Per-warp dump: S per (class, dim); Q lane-reduced; counts from lane 0.
    #pragma unroll
    for (int k = 0; k < NCLS; k++) shS[w][k * CHW + lane] = S[k];
    #pragma unroll
    for (int k = 0; k < NCLS; k++) {
        float qv = Q[k];
        #pragma unroll
        for (int off = 16; off; off >>= 1)
            qv += __shfl_down_sync(0xffffffffu, qv, off);
        if (lane == 0) shQ[w][k] = qv;
    }
    if (lane == 0) {
        #pragma unroll
        for (int k = 0; k < NCLS; k++) shC[w][k] = C[k];
    }
    __syncthreads();

    // 8-warp merge -> record (340 floats).
    float* rec = g_rec[b];
    for (int i = tid; i < NCLS * CHW; i += 256) {
        float s = 0.f;
        #pragma unroll
        for (int ww = 0; ww < 8; ww++) s += shS[ww][i];
        rec[i] = s;
    }
    if (tid < NCLS) {
        float q = 0.f; int cc = 0;
        #pragma unroll
        for (int ww = 0; ww < 8; ww++) { q += shQ[ww][tid]; cc += shC[ww][tid]; }
        rec[NCLS * CHW + tid] = q;
        rec[NCLS * CHW + NCLS + tid] = (float)cc;
    }

    // ---------------- Phase B election (last of 16 per chunk) -------------
    __threadfence();
    __syncthreads();
    if (tid == 0) flag = (atomicAdd(&g_gctr[c], 1) == NRG - 1) ? 1 : 0;
    __syncthreads();
    if (!flag) return;
    __threadfence();   // acquire peers' records

    // Sum 16 row-group records (one front-batched round trip).
    for (int i = tid; i < RECF; i += 256) {
        float v[NRG];
        #pragma unroll
        for (int j = 0; j < NRG; j++) v[j] = g_rec[j * NCH + c][i];
        float s = ((v[0] + v[1]) + (v[2] + v[3])) +
                  ((v[4] + v[5]) + (v[6] + v[7])) +
                  ((v[8] + v[9]) + (v[10] + v[11])) +
                  ((v[12] + v[13]) + (v[14] + v[15]));
        tot[i] = s;
    }
    if (w == 1) {
        x0c[lane] = x[c * CHW + lane];
        xNc[lane] = x[(size_t)(N - 1) * D + c * CHW + lane];
    }
    if (tid == 64) l0N[0] = lab[0];
    if (tid == 65) l0N[1] = lab[N - 1];
    __syncthreads();

    if (w == 0) {
        const int lab0 = l0N[0], labN = l0N[1];
        const float x0v = x0c[lane], xNv = xNc[lane];

        double dsame = 0.0;
        float satot = 0.f, sbtot = 0.f;
        #pragma unroll
        for (int l = 0; l < NCLS; l++) {
            float s  = tot[l * CHW + lane];
            float sa = s - ((l == labN) ? xNv : 0.f);   // rows i in [0, N-1)
            float sb = s - ((l == lab0) ? x0v : 0.f);   // cols j in [1, N)
            dsame += (double)sa * (double)sb;
            satot += sa; sbtot += sb;
        }
        double dall = (double)satot * (double)sbtot;
        double sq0  = (double)x0v * (double)x0v;
        double sqN  = (double)xNv * (double)xNv;

        #pragma unroll
        for (int off = 16; off; off >>= 1) {
            dsame += __shfl_down_sync(0xffffffffu, dsame, off);
            dall  += __shfl_down_sync(0xffffffffu, dall,  off);
            sq0   += __shfl_down_sync(0xffffffffu, sq0,   off);
            sqN   += __shfl_down_sync(0xffffffffu, sqN,   off);
        }

        if (lane == 0) {
            double term12 = 0.0;
            #pragma unroll
            for (int l = 0; l < NCLS; l++) {
                double Qc  = (double)tot[NCLS * CHW + l];          // chunk Q
                double cnt = (double)tot[NCLS * CHW + NCLS + l];   // global count
                double qA  = Qc - ((l == labN) ? sqN : 0.0);
                double qB  = Qc - ((l == lab0) ? sq0 : 0.0);
                double cA  = cnt - ((l == labN) ? 1.0 : 0.0);
                double cB  = cnt - ((l == lab0) ? 1.0 : 0.0);
                term12 += qA * (2.0 * cB - (double)(N - 1))
                        + qB * (2.0 * cA - (double)(N - 1));
            }
            g_contrib[c] = term12 - 2.0 * (2.0 * dsame - dall);
        }
    }

    // ---------------- Phase C election (last of 8 leaders) ----------------
    __threadfence();
    __syncthreads();
    if (tid == 0) flag = (atomicAdd(&g_fctr, 1) == NCH - 1) ? 1 : 0;
    __syncthreads();
    if (!flag) return;
    __threadfence();   // acquire contribs

    if (tid == 0) {
        double r = 0.0;
        #pragma unroll
        for (int c2 = 0; c2 < NCH; c2++) r += g_contrib[c2];  // fixed order
        res[0] = (float)(r * (0.5 / (double)N));              // COV*0.5/BATCH
    }
    // Reset counters for the next graph replay.
    if (tid < NCH) g_gctr[tid] = 0;
    if (tid == 0)  g_fctr = 0;
}

extern "C" void kernel_launch(void* const* d_in, const int* in_sizes, int n_in,
                              void* d_out, int out_size) {
    const float* x   = (const float*)d_in[0];
    const int*   lab = (const int*)d_in[1];
    float*       res = (float*)d_out;
    (void)in_sizes; (void)n_in; (void)out_size;

    k_all<<<NBK, 256>>>(x, lab, res);
}